// round 1
// baseline (speedup 1.0000x reference)
#include <cuda_runtime.h>

// Problem constants (fixed by the reference: B=16, N=1024, M=21, D=256, V=16)
#define BN_TOTAL (16 * 1024)
#define MPTS 21
#define PP 20      // M-1 points per polyline
#define D1 128
#define D2 256

__device__ int g_mask_is_byte;

// Detect whether map_mask is stored as 1-byte bool or 4-byte int32.
// int32 0/1 data has all-zero bytes at offsets not divisible by 4;
// random bool data has ~50% nonzero bytes everywhere. Scanning BN_TOTAL
// bytes is in-bounds under either interpretation.
__global__ void detect_mask_kernel(const unsigned char* __restrict__ m) {
    __shared__ int s_found;
    if (threadIdx.x == 0) s_found = 0;
    __syncthreads();
    int found = 0;
    for (int i = threadIdx.x; i < BN_TOTAL; i += blockDim.x) {
        if ((i & 3) != 0 && m[i] != 0) found = 1;
    }
    if (found) atomicOr(&s_found, 1);
    __syncthreads();
    if (threadIdx.x == 0) g_mask_is_byte = s_found;
}

__global__ __launch_bounds__(256) void map_encoder_kernel(
    const float* __restrict__ tgt,      // (B,N,21,2)
    const int* __restrict__ label,      // (B,N)
    const void* __restrict__ maskp,     // (B,N) bool or int32
    const float* __restrict__ W1, const float* __restrict__ b1,
    const float* __restrict__ g1, const float* __restrict__ be1,
    const float* __restrict__ m1, const float* __restrict__ v1,
    const float* __restrict__ W2, const float* __restrict__ b2,
    const float* __restrict__ W3, const float* __restrict__ b3,
    const float* __restrict__ g2, const float* __restrict__ be2,
    const float* __restrict__ m2, const float* __restrict__ v2,
    const float* __restrict__ W4, const float* __restrict__ b4,
    const float* __restrict__ temb,     // (16,256)
    const float* __restrict__ Wp1, const float* __restrict__ bp1,
    const float* __restrict__ Wp2, const float* __restrict__ bp2,
    const float* __restrict__ pcr,      // (6,)
    float* __restrict__ out)
{
    // Transposed intermediates: [channel][point], 20 floats (80B) per channel row
    // -> float4-aligned for LDS.128, broadcast reads across the warp.
    __shared__ float sm_hT[D2 * PP];    // stage2 output h, transposed     (20 KB)
    __shared__ float sm_buf[D2 * PP];   // h1T -> h2T -> hp (reused)       (20 KB)
    __shared__ float sm_vec[D2];        // pooled -> sine (reused)
    __shared__ float sm_pts[MPTS * 2 + 2];
    __shared__ float sm_feat[PP * 6];

    const int idx = blockIdx.x;
    const int t = threadIdx.x;

    bool mask;
    if (g_mask_is_byte)
        mask = ((const unsigned char*)maskp)[idx] != 0;
    else
        mask = ((const int*)maskp)[idx] != 0;

    float* __restrict__ feats_out = out;
    float* __restrict__ pos_out   = out + (size_t)BN_TOTAL * D2;
    float* __restrict__ mask_out  = out + (size_t)2 * BN_TOTAL * D2;

    if (!mask) {
        // map_feats = 0, x_pos = 0, ~mask = 1
        feats_out[(size_t)idx * D2 + t] = 0.0f;
        pos_out[(size_t)idx * D2 + t]   = 0.0f;
        if (t == 0) mask_out[idx] = 1.0f;
        return;
    }
    if (t == 0) mask_out[idx] = 0.0f;

    // ---- load points ----
    const float* pp = tgt + (size_t)idx * MPTS * 2;
    if (t < MPTS * 2) sm_pts[t] = pp[t];
    __syncthreads();

    // ---- feature construction: [rel(2), pv(2), orient(2)] for p=0..19 ----
    if (t < PP) {
        int p = t;
        float cx = sm_pts[10 * 2], cy = sm_pts[10 * 2 + 1];
        float x0 = sm_pts[2 * p],     y0 = sm_pts[2 * p + 1];
        float x1 = sm_pts[2 * p + 2], y1 = sm_pts[2 * p + 3];
        float pvx = x1 - x0, pvy = y1 - y0;
        // vnorm = ||pv|| + mask(=1 here) + 1e-6
        float vn = sqrtf(pvx * pvx + pvy * pvy) + 1.0f + 1e-6f;
        float inv = 1.0f / vn;
        sm_feat[p * 6 + 0] = x0 - cx;
        sm_feat[p * 6 + 1] = y0 - cy;
        sm_feat[p * 6 + 2] = pvx;
        sm_feat[p * 6 + 3] = pvy;
        sm_feat[p * 6 + 4] = pvx * inv;
        sm_feat[p * 6 + 5] = pvy * inv;
    }
    __syncthreads();

    // ---- stage 1: feat(20x6) @ W1(6x128) + b1 -> BN1 -> relu -> sm_buf = h1T[c][p] ----
    {
        int d = t & (D1 - 1);
        int pg = t >> 7;  // 0 or 1 -> rows [pg*10, pg*10+10)
        float w0 = W1[0 * D1 + d], w1 = W1[1 * D1 + d], w2 = W1[2 * D1 + d];
        float w3 = W1[3 * D1 + d], w4 = W1[4 * D1 + d], w5 = W1[5 * D1 + d];
        float s  = g1[d] * rsqrtf(v1[d] + 1e-5f);
        float sh = be1[d] - m1[d] * s + b1[d] * s;
        #pragma unroll
        for (int q = 0; q < 10; ++q) {
            int p = pg * 10 + q;
            const float* f = &sm_feat[p * 6];
            float lin = f[0] * w0 + f[1] * w1 + f[2] * w2
                      + f[3] * w3 + f[4] * w4 + f[5] * w5;
            sm_buf[d * PP + p] = fmaxf(lin * s + sh, 0.0f);
        }
    }
    __syncthreads();

    // ---- stage 2: h1(20x128) @ W2(128x256) + b2 ; pooled = max_p ----
    {
        float acc[PP];
        #pragma unroll
        for (int p = 0; p < PP; ++p) acc[p] = 0.0f;
        const float* wc = W2 + t;
        #pragma unroll 2
        for (int c = 0; c < D1; ++c) {
            float w = wc[c * D2];
            const float4* hv = (const float4*)&sm_buf[c * PP];
            #pragma unroll
            for (int q = 0; q < 5; ++q) {
                float4 h4 = hv[q];
                acc[4 * q + 0] = fmaf(h4.x, w, acc[4 * q + 0]);
                acc[4 * q + 1] = fmaf(h4.y, w, acc[4 * q + 1]);
                acc[4 * q + 2] = fmaf(h4.z, w, acc[4 * q + 2]);
                acc[4 * q + 3] = fmaf(h4.w, w, acc[4 * q + 3]);
            }
        }
        float bb = b2[t];
        float mx = -3.4e38f;
        #pragma unroll
        for (int p = 0; p < PP; ++p) {
            float v = acc[p] + bb;
            sm_hT[t * PP + p] = v;
            mx = fmaxf(mx, v);
        }
        sm_vec[t] = mx;  // pooled[t]
    }
    __syncthreads();

    // ---- stage 3: cat(20x512) @ W3(512x256) + b3 -> BN2 -> relu ----
    // cat = [h, broadcast(pooled)]  =>  h@W3[:256] + pooled@W3[256:]  (pooled term once)
    {
        float base = 0.0f;
        const float* wb = W3 + (size_t)D2 * D2 + t;
        #pragma unroll 4
        for (int c = 0; c < D2; ++c) base = fmaf(sm_vec[c], wb[c * D2], base);

        float acc[PP];
        #pragma unroll
        for (int p = 0; p < PP; ++p) acc[p] = 0.0f;
        const float* wc = W3 + t;
        #pragma unroll 2
        for (int c = 0; c < D2; ++c) {
            float w = wc[c * D2];
            const float4* hv = (const float4*)&sm_hT[c * PP];
            #pragma unroll
            for (int q = 0; q < 5; ++q) {
                float4 h4 = hv[q];
                acc[4 * q + 0] = fmaf(h4.x, w, acc[4 * q + 0]);
                acc[4 * q + 1] = fmaf(h4.y, w, acc[4 * q + 1]);
                acc[4 * q + 2] = fmaf(h4.z, w, acc[4 * q + 2]);
                acc[4 * q + 3] = fmaf(h4.w, w, acc[4 * q + 3]);
            }
        }
        float s  = g2[t] * rsqrtf(v2[t] + 1e-5f);
        float sh = be2[t] - m2[t] * s + b3[t] * s;
        #pragma unroll
        for (int p = 0; p < PP; ++p) {
            sm_buf[t * PP + p] = fmaxf((acc[p] + base) * s + sh, 0.0f);  // h2T
        }
    }
    __syncthreads();

    // ---- stage 4: h2(20x256) @ W4(256x256) + b4 -> max_p -> + type_emb ----
    {
        float acc[PP];
        #pragma unroll
        for (int p = 0; p < PP; ++p) acc[p] = 0.0f;
        const float* wc = W4 + t;
        #pragma unroll 2
        for (int c = 0; c < D2; ++c) {
            float w = wc[c * D2];
            const float4* hv = (const float4*)&sm_buf[c * PP];
            #pragma unroll
            for (int q = 0; q < 5; ++q) {
                float4 h4 = hv[q];
                acc[4 * q + 0] = fmaf(h4.x, w, acc[4 * q + 0]);
                acc[4 * q + 1] = fmaf(h4.y, w, acc[4 * q + 1]);
                acc[4 * q + 2] = fmaf(h4.z, w, acc[4 * q + 2]);
                acc[4 * q + 3] = fmaf(h4.w, w, acc[4 * q + 3]);
            }
        }
        float bb = b4[t];
        float mx = -3.4e38f;
        #pragma unroll
        for (int p = 0; p < PP; ++p) mx = fmaxf(mx, acc[p] + bb);
        int lb = label[idx];
        feats_out[(size_t)idx * D2 + t] = mx + temb[(size_t)lb * D2 + t];
    }

    // ---- positional embedding path ----
    // sine embed: sine = [ey(128), ex(128)], pair i: [sin(a_i), cos(a_i)],
    // a_i = pos * 2pi / 10000^(i/64)
    {
        float c0 = pcr[0], c1 = pcr[1], c3 = pcr[3], c4 = pcr[4];
        float posx = (sm_pts[10 * 2]     - c0) / (c3 - c0);
        float posy = (sm_pts[10 * 2 + 1] - c1) / (c4 - c1);
        int j = t & 127;
        float pos = (t < 128) ? posy : posx;
        int i = j >> 1;
        float freq = powf(10000.0f, (float)i * (1.0f / 64.0f));
        float arg = pos * 6.283185307179586f / freq;
        sm_vec[t] = (j & 1) ? cosf(arg) : sinf(arg);  // reuse: pooled is dead
    }
    __syncthreads();  // also fences stage-4 reads of sm_buf before hp overwrite

    // hp = relu(sine @ Wp1(256x512) + bp1): thread t owns columns t and t+256
    {
        float a0 = bp1[t], a1 = bp1[t + 256];
        const float* w0 = Wp1 + t;
        const float* w1 = Wp1 + t + 256;
        #pragma unroll 4
        for (int j = 0; j < 256; ++j) {
            float sj = sm_vec[j];
            a0 = fmaf(sj, w0[j * 512], a0);
            a1 = fmaf(sj, w1[j * 512], a1);
        }
        sm_buf[t]       = fmaxf(a0, 0.0f);
        sm_buf[t + 256] = fmaxf(a1, 0.0f);
    }
    __syncthreads();

    // pe = hp @ Wp2(512x256) + bp2
    {
        float acc = bp2[t];
        const float* wc = Wp2 + t;
        #pragma unroll 4
        for (int k = 0; k < 512; ++k) acc = fmaf(sm_buf[k], wc[k * D2], acc);
        pos_out[(size_t)idx * D2 + t] = acc;
    }
}

extern "C" void kernel_launch(void* const* d_in, const int* in_sizes, int n_in,
                              void* d_out, int out_size) {
    (void)in_sizes; (void)n_in; (void)out_size;

    const float* tgt   = (const float*)d_in[0];
    const int*   label = (const int*)d_in[1];
    const void*  maskp = d_in[2];
    const float* W1  = (const float*)d_in[3];
    const float* b1  = (const float*)d_in[4];
    const float* g1  = (const float*)d_in[5];
    const float* be1 = (const float*)d_in[6];
    const float* m1  = (const float*)d_in[7];
    const float* v1  = (const float*)d_in[8];
    const float* W2  = (const float*)d_in[9];
    const float* b2  = (const float*)d_in[10];
    const float* W3  = (const float*)d_in[11];
    const float* b3  = (const float*)d_in[12];
    const float* g2  = (const float*)d_in[13];
    const float* be2 = (const float*)d_in[14];
    const float* m2  = (const float*)d_in[15];
    const float* v2  = (const float*)d_in[16];
    const float* W4  = (const float*)d_in[17];
    const float* b4  = (const float*)d_in[18];
    const float* temb = (const float*)d_in[19];
    const float* Wp1 = (const float*)d_in[20];
    const float* bp1 = (const float*)d_in[21];
    const float* Wp2 = (const float*)d_in[22];
    const float* bp2 = (const float*)d_in[23];
    const float* pcr = (const float*)d_in[24];

    detect_mask_kernel<<<1, 256>>>((const unsigned char*)maskp);
    map_encoder_kernel<<<BN_TOTAL, 256>>>(
        tgt, label, maskp,
        W1, b1, g1, be1, m1, v1,
        W2, b2, W3, b3, g2, be2, m2, v2,
        W4, b4, temb, Wp1, bp1, Wp2, bp2, pcr,
        (float*)d_out);
}

// round 2
// speedup vs baseline: 1.2694x; 1.2694x over previous
#include <cuda_runtime.h>
#include <float.h>

// Problem constants (fixed by the reference: B=16, N=1024, M=21, D=256, V=16)
#define BN_TOTAL (16 * 1024)
#define MPTS 21
#define PP 20      // M-1 points per polyline
#define D1 128
#define D2 256

typedef unsigned long long ull;

// ---- packed f32x2 helpers (Blackwell FFMA2) ----
__device__ __forceinline__ ull pack2(float x, float y) {
    ull r;
    asm("mov.b64 %0, {%1, %2};" : "=l"(r) : "f"(x), "f"(y));
    return r;
}
__device__ __forceinline__ void unpack2(ull v, float& x, float& y) {
    asm("mov.b64 {%0, %1}, %2;" : "=f"(x), "=f"(y) : "l"(v));
}
__device__ __forceinline__ ull ffma2(ull a, ull b, ull c) {
    ull d;
    asm("fma.rn.f32x2 %0, %1, %2, %3;" : "=l"(d) : "l"(a), "l"(b), "l"(c));
    return d;
}

__device__ int g_mask_is_byte;

// Detect whether map_mask is stored as 1-byte bool or 4-byte int32.
__global__ void detect_mask_kernel(const unsigned char* __restrict__ m) {
    __shared__ int s_found;
    if (threadIdx.x == 0) s_found = 0;
    __syncthreads();
    int found = 0;
    for (int i = threadIdx.x; i < BN_TOTAL; i += blockDim.x) {
        if ((i & 3) != 0 && m[i] != 0) found = 1;
    }
    if (found) atomicOr(&s_found, 1);
    __syncthreads();
    if (threadIdx.x == 0) g_mask_is_byte = s_found;
}

__global__ __launch_bounds__(256) void map_encoder_kernel(
    const float* __restrict__ tgt,      // (B,N,21,2)
    const int* __restrict__ label,      // (B,N)
    const void* __restrict__ maskp,     // (B,N) bool or int32
    const float* __restrict__ W1, const float* __restrict__ b1,
    const float* __restrict__ g1, const float* __restrict__ be1,
    const float* __restrict__ m1, const float* __restrict__ v1,
    const float* __restrict__ W2, const float* __restrict__ b2,
    const float* __restrict__ W3, const float* __restrict__ b3,
    const float* __restrict__ g2, const float* __restrict__ be2,
    const float* __restrict__ m2, const float* __restrict__ v2,
    const float* __restrict__ W4, const float* __restrict__ b4,
    const float* __restrict__ temb,     // (16,256)
    const float* __restrict__ Wp1, const float* __restrict__ bp1,
    const float* __restrict__ Wp2, const float* __restrict__ bp2,
    const float* __restrict__ pcr,      // (6,)
    float* __restrict__ out)
{
    // Transposed intermediates: [channel][point], 20 floats (80B) per channel row.
    __shared__ float sm_hT[D2 * PP];    // stage2 output h, transposed     (20 KB)
    __shared__ float sm_buf[D2 * PP];   // h1T -> h2T -> hp (reused)       (20 KB)
    __shared__ float sm_vec[D2];        // pooled -> sine (reused)
    __shared__ float sm_part[2 * D2];   // partial maxes (two point-halves)
    __shared__ float sm_pts[MPTS * 2 + 2];
    __shared__ float sm_feat[PP * 6];

    const int idx = blockIdx.x;
    const int t = threadIdx.x;
    const int cp = t & 127;   // column pair: owns cols 2cp, 2cp+1
    const int ph = t >> 7;    // point half: points [ph*10, ph*10+10)

    bool mask;
    if (g_mask_is_byte)
        mask = ((const unsigned char*)maskp)[idx] != 0;
    else
        mask = ((const int*)maskp)[idx] != 0;

    float* __restrict__ feats_out = out;
    float* __restrict__ pos_out   = out + (size_t)BN_TOTAL * D2;
    float* __restrict__ mask_out  = out + (size_t)2 * BN_TOTAL * D2;

    if (!mask) {
        feats_out[(size_t)idx * D2 + t] = 0.0f;
        pos_out[(size_t)idx * D2 + t]   = 0.0f;
        if (t == 0) mask_out[idx] = 1.0f;
        return;
    }
    if (t == 0) mask_out[idx] = 0.0f;

    // ---- load points ----
    const float* pp = tgt + (size_t)idx * MPTS * 2;
    if (t < MPTS * 2) sm_pts[t] = pp[t];
    __syncthreads();

    // ---- feature construction ----
    if (t < PP) {
        int p = t;
        float cx = sm_pts[10 * 2], cy = sm_pts[10 * 2 + 1];
        float x0 = sm_pts[2 * p],     y0 = sm_pts[2 * p + 1];
        float x1 = sm_pts[2 * p + 2], y1 = sm_pts[2 * p + 3];
        float pvx = x1 - x0, pvy = y1 - y0;
        float vn = sqrtf(pvx * pvx + pvy * pvy) + 1.0f + 1e-6f;
        float inv = 1.0f / vn;
        sm_feat[p * 6 + 0] = x0 - cx;
        sm_feat[p * 6 + 1] = y0 - cy;
        sm_feat[p * 6 + 2] = pvx;
        sm_feat[p * 6 + 3] = pvy;
        sm_feat[p * 6 + 4] = pvx * inv;
        sm_feat[p * 6 + 5] = pvy * inv;
    }
    __syncthreads();

    // ---- stage 1: feat(20x6)@W1(6x128)+b1 -> BN1 -> relu -> sm_buf=h1T ----
    // thread (d = t&127, ph) computes channel d for its 10 points
    {
        int d = t & (D1 - 1);
        float w0 = W1[0 * D1 + d], w1 = W1[1 * D1 + d], w2 = W1[2 * D1 + d];
        float w3 = W1[3 * D1 + d], w4 = W1[4 * D1 + d], w5 = W1[5 * D1 + d];
        float s  = g1[d] * rsqrtf(v1[d] + 1e-5f);
        float sh = be1[d] - m1[d] * s + b1[d] * s;
        #pragma unroll
        for (int q = 0; q < 10; ++q) {
            int p = ph * 10 + q;
            const float* f = &sm_feat[p * 6];
            float lin = f[0] * w0 + f[1] * w1 + f[2] * w2
                      + f[3] * w3 + f[4] * w4 + f[5] * w5;
            sm_buf[d * PP + p] = fmaxf(lin * s + sh, 0.0f);
        }
    }
    __syncthreads();

    // ---- stage 2: h1(20x128)@W2(128x256)+b2 ; pooled = max_p ----
    // 2 cols x 5 point-pairs per thread, packed f32x2 MACs
    {
        ull acc0[5], acc1[5];
        #pragma unroll
        for (int q = 0; q < 5; ++q) { acc0[q] = 0ull; acc1[q] = 0ull; }
        #pragma unroll 2
        for (int c = 0; c < D1; ++c) {
            float2 w = *(const float2*)(W2 + c * D2 + 2 * cp);
            ull w0 = pack2(w.x, w.x);
            ull w1 = pack2(w.y, w.y);
            const ull* hv = (const ull*)(sm_buf + c * PP + ph * 10);
            #pragma unroll
            for (int q = 0; q < 5; ++q) {
                ull h = hv[q];
                acc0[q] = ffma2(h, w0, acc0[q]);
                acc1[q] = ffma2(h, w1, acc1[q]);
            }
        }
        float2 bb = *(const float2*)(b2 + 2 * cp);
        float mx0 = -FLT_MAX, mx1 = -FLT_MAX;
        #pragma unroll
        for (int q = 0; q < 5; ++q) {
            float a, b;
            unpack2(acc0[q], a, b);
            float v0 = a + bb.x, v1 = b + bb.x;
            mx0 = fmaxf(mx0, fmaxf(v0, v1));
            *(float2*)&sm_hT[(2 * cp) * PP + ph * 10 + 2 * q] = make_float2(v0, v1);
            unpack2(acc1[q], a, b);
            v0 = a + bb.y; v1 = b + bb.y;
            mx1 = fmaxf(mx1, fmaxf(v0, v1));
            *(float2*)&sm_hT[(2 * cp + 1) * PP + ph * 10 + 2 * q] = make_float2(v0, v1);
        }
        *(float2*)&sm_part[ph * D2 + 2 * cp] = make_float2(mx0, mx1);
    }
    __syncthreads();
    sm_vec[t] = fmaxf(sm_part[t], sm_part[D2 + t]);  // pooled
    __syncthreads();

    // ---- stage 3: cat(20x512)@W3(512x256)+b3 -> BN2 -> relu -> sm_buf=h2T ----
    // cat = [h, bcast(pooled)] => h@W3[:256] + pooled@W3[256:]
    {
        ull base = 0ull;
        #pragma unroll 4
        for (int c = 0; c < D2; ++c) {
            ull wb = *(const ull*)(W3 + (size_t)(D2 + c) * D2 + 2 * cp);
            float pc = sm_vec[c];
            base = ffma2(wb, pack2(pc, pc), base);
        }

        ull acc0[5], acc1[5];
        #pragma unroll
        for (int q = 0; q < 5; ++q) { acc0[q] = 0ull; acc1[q] = 0ull; }
        #pragma unroll 2
        for (int c = 0; c < D2; ++c) {
            float2 w = *(const float2*)(W3 + c * D2 + 2 * cp);
            ull w0 = pack2(w.x, w.x);
            ull w1 = pack2(w.y, w.y);
            const ull* hv = (const ull*)(sm_hT + c * PP + ph * 10);
            #pragma unroll
            for (int q = 0; q < 5; ++q) {
                ull h = hv[q];
                acc0[q] = ffma2(h, w0, acc0[q]);
                acc1[q] = ffma2(h, w1, acc1[q]);
            }
        }

        float2 gg  = *(const float2*)(g2  + 2 * cp);
        float2 vv  = *(const float2*)(v2  + 2 * cp);
        float2 mm  = *(const float2*)(m2  + 2 * cp);
        float2 ee  = *(const float2*)(be2 + 2 * cp);
        float2 b3v = *(const float2*)(b3  + 2 * cp);
        float s0 = gg.x * rsqrtf(vv.x + 1e-5f);
        float s1 = gg.y * rsqrtf(vv.y + 1e-5f);
        float sh0 = ee.x - mm.x * s0 + b3v.x * s0;
        float sh1 = ee.y - mm.y * s1 + b3v.y * s1;
        float bx, by;
        unpack2(base, bx, by);
        #pragma unroll
        for (int q = 0; q < 5; ++q) {
            float a, b;
            unpack2(acc0[q], a, b);
            *(float2*)&sm_buf[(2 * cp) * PP + ph * 10 + 2 * q] =
                make_float2(fmaxf((a + bx) * s0 + sh0, 0.0f),
                            fmaxf((b + bx) * s0 + sh0, 0.0f));
            unpack2(acc1[q], a, b);
            *(float2*)&sm_buf[(2 * cp + 1) * PP + ph * 10 + 2 * q] =
                make_float2(fmaxf((a + by) * s1 + sh1, 0.0f),
                            fmaxf((b + by) * s1 + sh1, 0.0f));
        }
    }
    __syncthreads();

    // ---- stage 4: h2(20x256)@W4(256x256)+b4 -> max_p ----
    {
        ull acc0[5], acc1[5];
        #pragma unroll
        for (int q = 0; q < 5; ++q) { acc0[q] = 0ull; acc1[q] = 0ull; }
        #pragma unroll 2
        for (int c = 0; c < D2; ++c) {
            float2 w = *(const float2*)(W4 + c * D2 + 2 * cp);
            ull w0 = pack2(w.x, w.x);
            ull w1 = pack2(w.y, w.y);
            const ull* hv = (const ull*)(sm_buf + c * PP + ph * 10);
            #pragma unroll
            for (int q = 0; q < 5; ++q) {
                ull h = hv[q];
                acc0[q] = ffma2(h, w0, acc0[q]);
                acc1[q] = ffma2(h, w1, acc1[q]);
            }
        }
        float2 bb = *(const float2*)(b4 + 2 * cp);
        float mx0 = -FLT_MAX, mx1 = -FLT_MAX;
        #pragma unroll
        for (int q = 0; q < 5; ++q) {
            float a, b;
            unpack2(acc0[q], a, b);
            mx0 = fmaxf(mx0, fmaxf(a, b));
            unpack2(acc1[q], a, b);
            mx1 = fmaxf(mx1, fmaxf(a, b));
        }
        *(float2*)&sm_part[ph * D2 + 2 * cp] = make_float2(mx0 + bb.x, mx1 + bb.y);
    }

    // ---- sine embedding (sm_vec is dead: pooled consumed in stage 3) ----
    {
        float c0 = pcr[0], c1 = pcr[1], c3 = pcr[3], c4 = pcr[4];
        float posx = (sm_pts[10 * 2]     - c0) / (c3 - c0);
        float posy = (sm_pts[10 * 2 + 1] - c1) / (c4 - c1);
        int j = t & 127;
        float pos = (t < 128) ? posy : posx;
        int i = j >> 1;
        float freq = powf(10000.0f, (float)i * (1.0f / 64.0f));
        float arg = pos * 6.283185307179586f / freq;
        sm_vec[t] = (j & 1) ? cosf(arg) : sinf(arg);
    }
    __syncthreads();  // fences: sm_part writes, sm_buf last reads, sm_vec writes

    // ---- stage-4 epilogue: combine halves, + type_emb ----
    {
        float mx = fmaxf(sm_part[t], sm_part[D2 + t]);
        int lb = label[idx];
        feats_out[(size_t)idx * D2 + t] = mx + temb[(size_t)lb * D2 + t];
    }

    // ---- hp = relu(sine @ Wp1(256x512) + bp1): thread t owns cols t, t+256 ----
    {
        float a0 = bp1[t], a1 = bp1[t + 256];
        const float* w0 = Wp1 + t;
        const float* w1 = Wp1 + t + 256;
        #pragma unroll 4
        for (int j = 0; j < 256; ++j) {
            float sj = sm_vec[j];
            a0 = fmaf(sj, w0[j * 512], a0);
            a1 = fmaf(sj, w1[j * 512], a1);
        }
        sm_buf[t]       = fmaxf(a0, 0.0f);
        sm_buf[t + 256] = fmaxf(a1, 0.0f);
    }
    __syncthreads();

    // ---- pe = hp @ Wp2(512x256) + bp2 ----
    {
        float acc = bp2[t];
        const float* wc = Wp2 + t;
        #pragma unroll 4
        for (int k = 0; k < 512; ++k) acc = fmaf(sm_buf[k], wc[k * D2], acc);
        pos_out[(size_t)idx * D2 + t] = acc;
    }
}

extern "C" void kernel_launch(void* const* d_in, const int* in_sizes, int n_in,
                              void* d_out, int out_size) {
    (void)in_sizes; (void)n_in; (void)out_size;

    const float* tgt   = (const float*)d_in[0];
    const int*   label = (const int*)d_in[1];
    const void*  maskp = d_in[2];
    const float* W1  = (const float*)d_in[3];
    const float* b1  = (const float*)d_in[4];
    const float* g1  = (const float*)d_in[5];
    const float* be1 = (const float*)d_in[6];
    const float* m1  = (const float*)d_in[7];
    const float* v1  = (const float*)d_in[8];
    const float* W2  = (const float*)d_in[9];
    const float* b2  = (const float*)d_in[10];
    const float* W3  = (const float*)d_in[11];
    const float* b3  = (const float*)d_in[12];
    const float* g2  = (const float*)d_in[13];
    const float* be2 = (const float*)d_in[14];
    const float* m2  = (const float*)d_in[15];
    const float* v2  = (const float*)d_in[16];
    const float* W4  = (const float*)d_in[17];
    const float* b4  = (const float*)d_in[18];
    const float* temb = (const float*)d_in[19];
    const float* Wp1 = (const float*)d_in[20];
    const float* bp1 = (const float*)d_in[21];
    const float* Wp2 = (const float*)d_in[22];
    const float* bp2 = (const float*)d_in[23];
    const float* pcr = (const float*)d_in[24];

    detect_mask_kernel<<<1, 256>>>((const unsigned char*)maskp);
    map_encoder_kernel<<<BN_TOTAL, 256>>>(
        tgt, label, maskp,
        W1, b1, g1, be1, m1, v1,
        W2, b2, W3, b3, g2, be2, m2, v2,
        W4, b4, temb, Wp1, bp1, Wp2, bp2, pcr,
        (float*)d_out);
}

// round 3
// speedup vs baseline: 1.5350x; 1.2093x over previous
#include <cuda_runtime.h>
#include <float.h>

// Problem constants (fixed by the reference: B=16, N=1024, M=21, D=256, V=16)
#define BN_TOTAL (16 * 1024)
#define MPTS 21
#define PP 20      // M-1 points per polyline
#define D1 128
#define D2 256

typedef unsigned long long ull;

// ---- packed f32x2 helpers (Blackwell FFMA2) ----
__device__ __forceinline__ ull pack2(float x, float y) {
    ull r;
    asm("mov.b64 %0, {%1, %2};" : "=l"(r) : "f"(x), "f"(y));
    return r;
}
__device__ __forceinline__ void unpack2(ull v, float& x, float& y) {
    asm("mov.b64 {%0, %1}, %2;" : "=f"(x), "=f"(y) : "l"(v));
}
__device__ __forceinline__ ull ffma2(ull a, ull b, ull c) {
    ull d;
    asm("fma.rn.f32x2 %0, %1, %2, %3;" : "=l"(d) : "l"(a), "l"(b), "l"(c));
    return d;
}

__device__ int g_mask_is_byte;

// Detect whether map_mask is stored as 1-byte bool or 4-byte int32.
__global__ void detect_mask_kernel(const unsigned char* __restrict__ m) {
    __shared__ int s_found;
    if (threadIdx.x == 0) s_found = 0;
    __syncthreads();
    int found = 0;
    for (int i = threadIdx.x; i < BN_TOTAL; i += blockDim.x) {
        if ((i & 3) != 0 && m[i] != 0) found = 1;
    }
    if (found) atomicOr(&s_found, 1);
    __syncthreads();
    if (threadIdx.x == 0) g_mask_is_byte = s_found;
}

// 128 threads/block. Thread t owns output columns (2t, 2t+1) of every GEMM
// and ALL 20 points -> max-pool is thread-local, h rows stream as LDS.128.
__global__ __launch_bounds__(128) void map_encoder_kernel(
    const float* __restrict__ tgt,      // (B,N,21,2)
    const int* __restrict__ label,      // (B,N)
    const void* __restrict__ maskp,     // (B,N) bool or int32
    const float* __restrict__ W1, const float* __restrict__ b1,
    const float* __restrict__ g1, const float* __restrict__ be1,
    const float* __restrict__ m1, const float* __restrict__ v1,
    const float* __restrict__ W2, const float* __restrict__ b2,
    const float* __restrict__ W3, const float* __restrict__ b3,
    const float* __restrict__ g2, const float* __restrict__ be2,
    const float* __restrict__ m2, const float* __restrict__ v2,
    const float* __restrict__ W4, const float* __restrict__ b4,
    const float* __restrict__ temb,     // (16,256)
    const float* __restrict__ Wp1, const float* __restrict__ bp1,
    const float* __restrict__ Wp2, const float* __restrict__ bp2,
    const float* __restrict__ pcr,      // (6,)
    float* __restrict__ out)
{
    // [channel][point] transposed intermediates; 20-float (80B) rows are
    // 16B-aligned (80 = 5*16) -> 5x LDS.128 per row.
    __shared__ float sm_hT[D2 * PP];    // stage2 output h                 (20 KB)
    __shared__ float sm_buf[D2 * PP];   // h1T -> h2T -> hp(512) (reused)  (20 KB)
    __shared__ float sm_vec[D2];        // pooled -> sine (reused)
    __shared__ float sm_pts[MPTS * 2 + 2];
    __shared__ float sm_feat[PP * 6];

    const int idx = blockIdx.x;
    const int t = threadIdx.x;          // 0..127; owns cols 2t, 2t+1

    bool mask;
    if (g_mask_is_byte)
        mask = ((const unsigned char*)maskp)[idx] != 0;
    else
        mask = ((const int*)maskp)[idx] != 0;

    float* __restrict__ feats_out = out;
    float* __restrict__ pos_out   = out + (size_t)BN_TOTAL * D2;
    float* __restrict__ mask_out  = out + (size_t)2 * BN_TOTAL * D2;

    if (!mask) {
        *(float2*)&feats_out[(size_t)idx * D2 + 2 * t] = make_float2(0.0f, 0.0f);
        *(float2*)&pos_out[(size_t)idx * D2 + 2 * t]   = make_float2(0.0f, 0.0f);
        if (t == 0) mask_out[idx] = 1.0f;
        return;
    }
    if (t == 0) mask_out[idx] = 0.0f;

    // ---- load points ----
    const float* pp = tgt + (size_t)idx * MPTS * 2;
    if (t < MPTS * 2) sm_pts[t] = pp[t];
    __syncthreads();

    // ---- feature construction ----
    if (t < PP) {
        int p = t;
        float cx = sm_pts[10 * 2], cy = sm_pts[10 * 2 + 1];
        float x0 = sm_pts[2 * p],     y0 = sm_pts[2 * p + 1];
        float x1 = sm_pts[2 * p + 2], y1 = sm_pts[2 * p + 3];
        float pvx = x1 - x0, pvy = y1 - y0;
        float vn = sqrtf(pvx * pvx + pvy * pvy) + 1.0f + 1e-6f;
        float inv = 1.0f / vn;
        sm_feat[p * 6 + 0] = x0 - cx;
        sm_feat[p * 6 + 1] = y0 - cy;
        sm_feat[p * 6 + 2] = pvx;
        sm_feat[p * 6 + 3] = pvy;
        sm_feat[p * 6 + 4] = pvx * inv;
        sm_feat[p * 6 + 5] = pvy * inv;
    }
    __syncthreads();

    // ---- stage 1: feat(20x6)@W1(6x128)+b1 -> BN1 -> relu -> sm_buf=h1T ----
    // thread t = channel t (t < 128), all 20 points
    {
        int d = t;
        float w0 = W1[0 * D1 + d], w1 = W1[1 * D1 + d], w2 = W1[2 * D1 + d];
        float w3 = W1[3 * D1 + d], w4 = W1[4 * D1 + d], w5 = W1[5 * D1 + d];
        float s  = g1[d] * rsqrtf(v1[d] + 1e-5f);
        float sh = be1[d] - m1[d] * s + b1[d] * s;
        #pragma unroll
        for (int p = 0; p < PP; ++p) {
            const float* f = &sm_feat[p * 6];
            float lin = f[0] * w0 + f[1] * w1 + f[2] * w2
                      + f[3] * w3 + f[4] * w4 + f[5] * w5;
            sm_buf[d * PP + p] = fmaxf(lin * s + sh, 0.0f);
        }
    }
    __syncthreads();

    // ---- stage 2: h1(20x128)@W2(128x256)+b2 ; pooled = max_p (thread-local) ----
    {
        ull acc0[10], acc1[10];
        #pragma unroll
        for (int q = 0; q < 10; ++q) { acc0[q] = 0ull; acc1[q] = 0ull; }
        #pragma unroll 2
        for (int c = 0; c < D1; ++c) {
            float2 w = *(const float2*)(W2 + c * D2 + 2 * t);
            ull w0 = pack2(w.x, w.x);
            ull w1 = pack2(w.y, w.y);
            const ulonglong2* hv = (const ulonglong2*)(sm_buf + c * PP);
            #pragma unroll
            for (int q = 0; q < 5; ++q) {
                ulonglong2 h = hv[q];
                acc0[2 * q]     = ffma2(h.x, w0, acc0[2 * q]);
                acc0[2 * q + 1] = ffma2(h.y, w0, acc0[2 * q + 1]);
                acc1[2 * q]     = ffma2(h.x, w1, acc1[2 * q]);
                acc1[2 * q + 1] = ffma2(h.y, w1, acc1[2 * q + 1]);
            }
        }
        float2 bb = *(const float2*)(b2 + 2 * t);
        float* r0 = sm_hT + (2 * t) * PP;
        float* r1 = sm_hT + (2 * t + 1) * PP;
        float mx0 = -FLT_MAX, mx1 = -FLT_MAX;
        #pragma unroll
        for (int q = 0; q < 10; ++q) {
            float a, b;
            unpack2(acc0[q], a, b);
            a += bb.x; b += bb.x;
            mx0 = fmaxf(mx0, fmaxf(a, b));
            *(float2*)&r0[2 * q] = make_float2(a, b);
            unpack2(acc1[q], a, b);
            a += bb.y; b += bb.y;
            mx1 = fmaxf(mx1, fmaxf(a, b));
            *(float2*)&r1[2 * q] = make_float2(a, b);
        }
        *(float2*)&sm_vec[2 * t] = make_float2(mx0, mx1);  // pooled
    }
    __syncthreads();

    // ---- stage 3: cat(20x512)@W3(512x256)+b3 -> BN2 -> relu -> sm_buf=h2T ----
    // cat = [h, bcast(pooled)] => h@W3[:256] + pooled@W3[256:]
    {
        ull base = 0ull;
        #pragma unroll 4
        for (int c = 0; c < D2; ++c) {
            ull wb = *(const ull*)(W3 + (size_t)(D2 + c) * D2 + 2 * t);
            float pc = sm_vec[c];
            base = ffma2(wb, pack2(pc, pc), base);
        }
        float bx, by;
        unpack2(base, bx, by);

        ull acc0[10], acc1[10];
        #pragma unroll
        for (int q = 0; q < 10; ++q) { acc0[q] = 0ull; acc1[q] = 0ull; }
        #pragma unroll 2
        for (int c = 0; c < D2; ++c) {
            float2 w = *(const float2*)(W3 + c * D2 + 2 * t);
            ull w0 = pack2(w.x, w.x);
            ull w1 = pack2(w.y, w.y);
            const ulonglong2* hv = (const ulonglong2*)(sm_hT + c * PP);
            #pragma unroll
            for (int q = 0; q < 5; ++q) {
                ulonglong2 h = hv[q];
                acc0[2 * q]     = ffma2(h.x, w0, acc0[2 * q]);
                acc0[2 * q + 1] = ffma2(h.y, w0, acc0[2 * q + 1]);
                acc1[2 * q]     = ffma2(h.x, w1, acc1[2 * q]);
                acc1[2 * q + 1] = ffma2(h.y, w1, acc1[2 * q + 1]);
            }
        }

        float2 gg  = *(const float2*)(g2  + 2 * t);
        float2 vv  = *(const float2*)(v2  + 2 * t);
        float2 mm  = *(const float2*)(m2  + 2 * t);
        float2 ee  = *(const float2*)(be2 + 2 * t);
        float2 b3v = *(const float2*)(b3  + 2 * t);
        float s0 = gg.x * rsqrtf(vv.x + 1e-5f);
        float s1 = gg.y * rsqrtf(vv.y + 1e-5f);
        float sh0 = ee.x - mm.x * s0 + b3v.x * s0;
        float sh1 = ee.y - mm.y * s1 + b3v.y * s1;
        float* r0 = sm_buf + (2 * t) * PP;
        float* r1 = sm_buf + (2 * t + 1) * PP;
        #pragma unroll
        for (int q = 0; q < 10; ++q) {
            float a, b;
            unpack2(acc0[q], a, b);
            *(float2*)&r0[2 * q] =
                make_float2(fmaxf((a + bx) * s0 + sh0, 0.0f),
                            fmaxf((b + bx) * s0 + sh0, 0.0f));
            unpack2(acc1[q], a, b);
            *(float2*)&r1[2 * q] =
                make_float2(fmaxf((a + by) * s1 + sh1, 0.0f),
                            fmaxf((b + by) * s1 + sh1, 0.0f));
        }
    }
    __syncthreads();

    // ---- stage 4: h2(20x256)@W4(256x256)+b4 -> max_p -> +type_emb -> out ----
    {
        ull acc0[10], acc1[10];
        #pragma unroll
        for (int q = 0; q < 10; ++q) { acc0[q] = 0ull; acc1[q] = 0ull; }
        #pragma unroll 2
        for (int c = 0; c < D2; ++c) {
            float2 w = *(const float2*)(W4 + c * D2 + 2 * t);
            ull w0 = pack2(w.x, w.x);
            ull w1 = pack2(w.y, w.y);
            const ulonglong2* hv = (const ulonglong2*)(sm_buf + c * PP);
            #pragma unroll
            for (int q = 0; q < 5; ++q) {
                ulonglong2 h = hv[q];
                acc0[2 * q]     = ffma2(h.x, w0, acc0[2 * q]);
                acc0[2 * q + 1] = ffma2(h.y, w0, acc0[2 * q + 1]);
                acc1[2 * q]     = ffma2(h.x, w1, acc1[2 * q]);
                acc1[2 * q + 1] = ffma2(h.y, w1, acc1[2 * q + 1]);
            }
        }
        float2 bb = *(const float2*)(b4 + 2 * t);
        float mx0 = -FLT_MAX, mx1 = -FLT_MAX;
        #pragma unroll
        for (int q = 0; q < 10; ++q) {
            float a, b;
            unpack2(acc0[q], a, b);
            mx0 = fmaxf(mx0, fmaxf(a, b));
            unpack2(acc1[q], a, b);
            mx1 = fmaxf(mx1, fmaxf(a, b));
        }
        int lb = label[idx];
        float2 tv = *(const float2*)(temb + (size_t)lb * D2 + 2 * t);
        *(float2*)&feats_out[(size_t)idx * D2 + 2 * t] =
            make_float2(mx0 + bb.x + tv.x, mx1 + bb.y + tv.y);
    }

    // ---- sine embedding: thread t computes sine[2t], sine[2t+1] ----
    // (sm_vec pooled is dead after stage-3 base term)
    {
        float c0 = pcr[0], c1 = pcr[1], c3 = pcr[3], c4 = pcr[4];
        float posx = (sm_pts[10 * 2]     - c0) / (c3 - c0);
        float posy = (sm_pts[10 * 2 + 1] - c1) / (c4 - c1);
        float pos = (t < 64) ? posy : posx;   // s=2t<128 <=> t<64
        int i = t & 63;
        float freq = powf(10000.0f, (float)i * (1.0f / 64.0f));
        float arg = pos * 6.283185307179586f / freq;
        float sn, cs;
        sincosf(arg, &sn, &cs);
        *(float2*)&sm_vec[2 * t] = make_float2(sn, cs);  // even=sin, odd=cos
    }
    __syncthreads();  // fences stage-4 sm_buf reads + sine writes

    // ---- hp = relu(sine @ Wp1(256x512) + bp1): cols (2t,2t+1),(2t+256,2t+257) ----
    {
        ull a0 = pack2(bp1[2 * t], bp1[2 * t + 1]);
        ull a1 = pack2(bp1[2 * t + 256], bp1[2 * t + 257]);
        #pragma unroll 4
        for (int j = 0; j < 256; ++j) {
            float sj = sm_vec[j];
            ull sd = pack2(sj, sj);
            a0 = ffma2(*(const ull*)(Wp1 + j * 512 + 2 * t), sd, a0);
            a1 = ffma2(*(const ull*)(Wp1 + j * 512 + 2 * t + 256), sd, a1);
        }
        float a, b;
        unpack2(a0, a, b);
        *(float2*)&sm_buf[2 * t] = make_float2(fmaxf(a, 0.0f), fmaxf(b, 0.0f));
        unpack2(a1, a, b);
        *(float2*)&sm_buf[2 * t + 256] = make_float2(fmaxf(a, 0.0f), fmaxf(b, 0.0f));
    }
    __syncthreads();

    // ---- pe = hp @ Wp2(512x256) + bp2 ----
    {
        ull acc = pack2(bp2[2 * t], bp2[2 * t + 1]);
        #pragma unroll 4
        for (int k = 0; k < 512; ++k) {
            float hk = sm_buf[k];
            acc = ffma2(*(const ull*)(Wp2 + k * D2 + 2 * t), pack2(hk, hk), acc);
        }
        float a, b;
        unpack2(acc, a, b);
        *(float2*)&pos_out[(size_t)idx * D2 + 2 * t] = make_float2(a, b);
    }
}

extern "C" void kernel_launch(void* const* d_in, const int* in_sizes, int n_in,
                              void* d_out, int out_size) {
    (void)in_sizes; (void)n_in; (void)out_size;

    const float* tgt   = (const float*)d_in[0];
    const int*   label = (const int*)d_in[1];
    const void*  maskp = d_in[2];
    const float* W1  = (const float*)d_in[3];
    const float* b1  = (const float*)d_in[4];
    const float* g1  = (const float*)d_in[5];
    const float* be1 = (const float*)d_in[6];
    const float* m1  = (const float*)d_in[7];
    const float* v1  = (const float*)d_in[8];
    const float* W2  = (const float*)d_in[9];
    const float* b2  = (const float*)d_in[10];
    const float* W3  = (const float*)d_in[11];
    const float* b3  = (const float*)d_in[12];
    const float* g2  = (const float*)d_in[13];
    const float* be2 = (const float*)d_in[14];
    const float* m2  = (const float*)d_in[15];
    const float* v2  = (const float*)d_in[16];
    const float* W4  = (const float*)d_in[17];
    const float* b4  = (const float*)d_in[18];
    const float* temb = (const float*)d_in[19];
    const float* Wp1 = (const float*)d_in[20];
    const float* bp1 = (const float*)d_in[21];
    const float* Wp2 = (const float*)d_in[22];
    const float* bp2 = (const float*)d_in[23];
    const float* pcr = (const float*)d_in[24];

    detect_mask_kernel<<<1, 256>>>((const unsigned char*)maskp);
    map_encoder_kernel<<<BN_TOTAL, 128>>>(
        tgt, label, maskp,
        W1, b1, g1, be1, m1, v1,
        W2, b2, W3, b3, g2, be2, m2, v2,
        W4, b4, temb, Wp1, bp1, Wp2, bp2, pcr,
        (float*)d_out);
}